// round 6
// baseline (speedup 1.0000x reference)
#include <cuda_runtime.h>
#include <cuda_bf16.h>
#include <cstdint>

#define B_ 16
#define D_ 128
#define M_ 2048
#define N_ 4096
#define NT 32                 // 128-row tiles per batch
#define CHUNKS 80             // sum_i ceil((32-i)/8)
#define TILEB 16384           // 128 rows * 128 bytes (fp8)

// Normalized rows scaled by sqrt(2*log2 e), e4m3 fp8, [b][n][d] row-major
__device__ __align__(16) unsigned char g_zn[(size_t)B_ * N_ * D_];
// Per-row sum(2^d') and positive d' accumulators  (d' = 2*log2(e)*cos)
__device__ float g_rowsum[B_ * N_];
__device__ float g_rowpos[B_ * N_];

// ---------------------------------------------------------------- zero scratch
__global__ void zero_kernel(float* out, int n_out) {
    int i = blockIdx.x * blockDim.x + threadIdx.x;
    if (i < B_ * N_) { g_rowsum[i] = 0.f; g_rowpos[i] = 0.f; }
    if (i < n_out) out[i] = 0.f;
}

// ------------------------------------------------------- normalize + transpose
// Z[b][d][m] fp32 -> g_zn[b][n][d] e4m3, scaled so MMA gives d' directly.
__global__ void normalize_kernel(const float* __restrict__ Zi,
                                 const float* __restrict__ Zj) {
    __shared__ float tile[D_][33];
    __shared__ float part[8][32];
    __shared__ float rnorm_s[32];
    const int m0  = blockIdx.x * 32;
    const int src = blockIdx.y;
    const int b   = blockIdx.z;
    const float* Z = src ? Zj : Zi;
    const int tid = threadIdx.x;
    const int tx = tid & 31, ty = tid >> 5;

    const float* base = Z + (size_t)b * D_ * M_ + m0 + tx;
    float ss = 0.f;
#pragma unroll
    for (int d = ty; d < D_; d += 8) {
        float v = base[(size_t)d * M_];
        tile[d][tx] = v;
        ss += v * v;
    }
    part[ty][tx] = ss;
    __syncthreads();
    if (ty == 0) {
        float s = 0.f;
#pragma unroll
        for (int k = 0; k < 8; k++) s += part[k][tx];
        rnorm_s[tx] = 1.6986437717f / fmaxf(sqrtf(s), 1e-8f);  // sqrt(2*log2 e)
    }
    __syncthreads();

    unsigned* out32 = reinterpret_cast<unsigned*>(g_zn);
    const size_t nbase = (size_t)b * N_ + (size_t)src * M_ + m0;
#pragma unroll
    for (int it = 0; it < 4; it++) {
        int idx = it * 256 + tid;      // 0..1023
        int r = idx >> 5;              // row 0..31
        int q = idx & 31;              // d-quad 0..31
        float rn = rnorm_s[r];
        float v0 = tile[4 * q][r] * rn;
        float v1 = tile[4 * q + 1][r] * rn;
        float v2 = tile[4 * q + 2][r] * rn;
        float v3 = tile[4 * q + 3][r] * rn;
        unsigned short p0, p1;   // low byte = 2nd src operand
        asm("cvt.rn.satfinite.e4m3x2.f32 %0, %1, %2;" : "=h"(p0) : "f"(v1), "f"(v0));
        asm("cvt.rn.satfinite.e4m3x2.f32 %0, %1, %2;" : "=h"(p1) : "f"(v3), "f"(v2));
        out32[(nbase + r) * 32 + q] = (unsigned)p0 | ((unsigned)p1 << 16);
    }
}

// ------------------------------------------------------------------- helpers
__device__ __forceinline__ unsigned swz_off(int row, int ch) {
    // 128B rows, 8 chunks of 16B, XOR swizzle -> conflict-free ldmatrix
    return (unsigned)(row * 128 + ((ch ^ (row & 7)) << 4));
}
__device__ __forceinline__ void ldsm_x4(unsigned addr, unsigned& r0, unsigned& r1,
                                        unsigned& r2, unsigned& r3) {
    asm volatile("ldmatrix.sync.aligned.m8n8.x4.shared.b16 {%0,%1,%2,%3}, [%4];"
                 : "=r"(r0), "=r"(r1), "=r"(r2), "=r"(r3) : "r"(addr));
}
__device__ __forceinline__ void mma_fp8(float* c, const unsigned* a,
                                        unsigned b0, unsigned b1) {
    asm volatile("mma.sync.aligned.m16n8k32.row.col.f32.e4m3.e4m3.f32 "
                 "{%0,%1,%2,%3}, {%4,%5,%6,%7}, {%8,%9}, {%0,%1,%2,%3};"
                 : "+f"(c[0]), "+f"(c[1]), "+f"(c[2]), "+f"(c[3])
                 : "r"(a[0]), "r"(a[1]), "r"(a[2]), "r"(a[3]), "r"(b0), "r"(b1));
}
__device__ __forceinline__ float ex2f(float x) {
    float y; asm("ex2.approx.f32 %0, %1;" : "=f"(y) : "f"(x)); return y;
}
__device__ __forceinline__ float lg2f(float x) {
    float y; asm("lg2.approx.f32 %0, %1;" : "=f"(y) : "f"(x)); return y;
}
__device__ __forceinline__ void cp16(unsigned dst, const void* src) {
    asm volatile("cp.async.cg.shared.global [%0], [%1], 16;"
                 :: "r"(dst), "l"(src) : "memory");
}
#define CP_COMMIT() asm volatile("cp.async.commit_group;" ::: "memory")

__device__ __forceinline__ void load_tile(unsigned sdst, const char* gsrc, int tid) {
#pragma unroll
    for (int it = 0; it < 4; it++) {
        int idx = it * 256 + tid;          // 1024 x 16B chunks
        int row = idx >> 3, ch = idx & 7;
        cp16(sdst + swz_off(row, ch), gsrc + row * 128 + ch * 16);
    }
}

// ------------------------------------------------------------------ main pass
// One CTA per (row-tile i, strip of up to 8 col-tiles). A resident,
// B triple-buffered, prefetch distance 2. Symmetry: tile (i,j) feeds rows of i
// (row sums, registers) AND rows of j (column sums via csum staging).
__global__ __launch_bounds__(256, 2) void simclr_chunk_kernel() {
    extern __shared__ char smem[];          // A 16K | B0 | B1 | B2 (16K each)
    __shared__ float csum[4][128];
    __shared__ float asum[128], apos[128];

    const int b = blockIdx.y;
    int rem = blockIdx.x, ti = 0;
    for (;;) { int c = (NT - ti + 7) >> 3; if (rem < c) break; rem -= c; ti++; }
    const int j0 = ti + rem * 8;
    const int nt = min(8, NT - j0);

    const int tid = threadIdx.x;
    const int lane = tid & 31, w = tid >> 5;
    const int rowA = (w >> 1) * 32;
    const int colB = (w & 1) * 64;

    unsigned sA = (unsigned)__cvta_generic_to_shared(smem);
    unsigned sB[3] = {sA + 16384, sA + 32768, sA + 49152};

    if (tid < 128) { asum[tid] = 0.f; apos[tid] = 0.f; }

    const char* zb = (const char*)(g_zn + (size_t)b * N_ * D_);
    // group 0: A + B0 ; group 1: B1 ; group 2: B2
    load_tile(sA, zb + (size_t)ti * TILEB, tid);
    load_tile(sB[0], zb + (size_t)j0 * TILEB, tid);
    CP_COMMIT();
    if (nt > 1) load_tile(sB[1], zb + (size_t)(j0 + 1) * TILEB, tid);
    CP_COMMIT();
    if (nt > 2) load_tile(sB[2], zb + (size_t)(j0 + 2) * TILEB, tid);
    CP_COMMIT();

    float rs[4] = {0.f, 0.f, 0.f, 0.f};
    float* rowsum_b = g_rowsum + b * N_;
    float* rowpos_b = g_rowpos + b * N_;

    int bufi = 0;   // t % 3
    for (int t = 0; t < nt; t++) {
        asm volatile("cp.async.wait_group 2;" ::: "memory");
        __syncthreads();

        const int j = j0 + t;
        const unsigned sBt = sB[bufi];
        const bool dt = (j == ti);
        const bool pt = (j == ti + 16);

        float acc[2][8][4];
#pragma unroll
        for (int mi = 0; mi < 2; mi++)
#pragma unroll
            for (int ng = 0; ng < 8; ng++)
#pragma unroll
                for (int q = 0; q < 4; q++) acc[mi][ng][q] = 0.f;

#pragma unroll
        for (int k = 0; k < 4; k++) {            // k32 per step
            unsigned a[2][4], bb[4][4];
            const int ch = 2 * k + (lane >> 4);
            const int rl = lane & 15;
#pragma unroll
            for (int mi = 0; mi < 2; mi++)
                ldsm_x4(sA + swz_off(rowA + mi * 16 + rl, ch),
                        a[mi][0], a[mi][1], a[mi][2], a[mi][3]);
#pragma unroll
            for (int g = 0; g < 4; g++)
                ldsm_x4(sBt + swz_off(colB + g * 16 + rl, ch),
                        bb[g][0], bb[g][1], bb[g][2], bb[g][3]);
#pragma unroll
            for (int mi = 0; mi < 2; mi++)
#pragma unroll
                for (int ng = 0; ng < 8; ng++)
                    mma_fp8(acc[mi][ng], a[mi],
                            bb[ng >> 1][ng & 1], bb[ng >> 1][(ng & 1) + 2]);
        }

        // transform: acc <- exp2(d'); diag/pos special handling
        if (!dt && !pt) {
#pragma unroll
            for (int mi = 0; mi < 2; mi++)
#pragma unroll
                for (int ng = 0; ng < 8; ng++)
#pragma unroll
                    for (int q = 0; q < 4; q++)
                        acc[mi][ng][q] = ex2f(acc[mi][ng][q]);
        } else {
#pragma unroll
            for (int mi = 0; mi < 2; mi++)
#pragma unroll
                for (int ng = 0; ng < 8; ng++)
#pragma unroll
                    for (int q = 0; q < 4; q++) {
                        const int lr = rowA + mi * 16 + (q >> 1) * 8 + (lane >> 2);
                        const int lc = colB + ng * 8 + ((lane & 3) << 1) + (q & 1);
                        const float dv = acc[mi][ng][q];
                        if (pt && lr == lc) {
                            atomicAdd(&apos[lr], dv);
                            atomicAdd(&rowpos_b[j * 128 + lr], dv);
                        }
                        acc[mi][ng][q] = (dt && lr == lc) ? 0.f : ex2f(dv);
                    }
        }

        // row partials (registers, reduced at CTA end)
#pragma unroll
        for (int idx = 0; idx < 4; idx++) {
            const int mi = idx >> 1, qh = idx & 1;
            float r = 0.f;
#pragma unroll
            for (int ng = 0; ng < 8; ng++)
                r += acc[mi][ng][2 * qh] + acc[mi][ng][2 * qh + 1];
            rs[idx] += r;
        }

        // column partials -> csum (conflict-free slots)
#pragma unroll
        for (int ng = 0; ng < 8; ng++)
#pragma unroll
            for (int ql = 0; ql < 2; ql++) {
                float cs = acc[0][ng][ql] + acc[0][ng][ql + 2]
                         + acc[1][ng][ql] + acc[1][ng][ql + 2];
                cs += __shfl_xor_sync(0xffffffffu, cs, 4);
                cs += __shfl_xor_sync(0xffffffffu, cs, 8);
                cs += __shfl_xor_sync(0xffffffffu, cs, 16);
                if (lane < 4)
                    csum[w >> 1][colB + ng * 8 + lane * 2 + ql] = cs;
            }
        __syncthreads();

        // prefetch B_{t+3} into the buffer just consumed
        if (t + 3 < nt)
            load_tile(sB[bufi], zb + (size_t)(j + 3) * TILEB, tid);
        CP_COMMIT();

        // push column sums to rows of tile j (skip diagonal tile)
        if (!dt && tid < 128) {
            float cs = (csum[0][tid] + csum[1][tid])
                     + (csum[2][tid] + csum[3][tid]);
            atomicAdd(&rowsum_b[j * 128 + tid], cs);
        }
        bufi = (bufi == 2) ? 0 : bufi + 1;
    }

    // CTA-end: quad-reduce row partials, combine, push rows of tile ti
#pragma unroll
    for (int idx = 0; idx < 4; idx++) {
        rs[idx] += __shfl_xor_sync(0xffffffffu, rs[idx], 1);
        rs[idx] += __shfl_xor_sync(0xffffffffu, rs[idx], 2);
    }
    if ((lane & 3) == 0) {
#pragma unroll
        for (int idx = 0; idx < 4; idx++)
            atomicAdd(&asum[rowA + (idx >> 1) * 16 + (idx & 1) * 8 + (lane >> 2)],
                      rs[idx]);
    }
    __syncthreads();
    const bool had_pt = (ti + 16 >= j0) && (ti + 16 < j0 + nt);
    if (tid < 128) {
        atomicAdd(&rowsum_b[ti * 128 + tid], asum[tid]);
        if (had_pt) atomicAdd(&rowpos_b[ti * 128 + tid], apos[tid]);
    }
}

// -------------------------------------------------------------------- finalize
// loss_row = ln2 * (log2(rowsum) - rowpos)
__global__ void finalize_kernel(float* __restrict__ out) {
    const int r = blockIdx.x * 256 + threadIdx.x;
    float v = 0.6931471805599453f * (lg2f(g_rowsum[r]) - g_rowpos[r]);
#pragma unroll
    for (int o = 16; o > 0; o >>= 1) v += __shfl_xor_sync(0xffffffffu, v, o);
    __shared__ float red[8];
    const int w = threadIdx.x >> 5;
    if ((threadIdx.x & 31) == 0) red[w] = v;
    __syncthreads();
    if (threadIdx.x == 0) {
        float s = 0.f;
#pragma unroll
        for (int k = 0; k < 8; k++) s += red[k];
        atomicAdd(out, s * (1.f / ((float)B_ * (float)N_)));
    }
}

// ----------------------------------------------------------------- entry point
extern "C" void kernel_launch(void* const* d_in, const int* in_sizes, int n_in,
                              void* d_out, int out_size) {
    const float* Zi = (const float*)d_in[0];
    const float* Zj = (const float*)d_in[1];
    float* out = (float*)d_out;
    (void)in_sizes; (void)n_in;

    cudaFuncSetAttribute(simclr_chunk_kernel,
                         cudaFuncAttributeMaxDynamicSharedMemorySize, 65536);

    zero_kernel<<<(B_ * N_ + 255) / 256, 256>>>(out, out_size);
    normalize_kernel<<<dim3(M_ / 32, 2, B_), 256>>>(Zi, Zj);
    simclr_chunk_kernel<<<dim3(CHUNKS, B_), 256, 65536>>>();
    finalize_kernel<<<B_ * N_ / 256, 256>>>(out);
}

// round 7
// speedup vs baseline: 1.9940x; 1.9940x over previous
#include <cuda_runtime.h>
#include <cuda_bf16.h>
#include <cstdint>

#define B_ 16
#define D_ 128
#define M_ 2048
#define N_ 4096
#define NT 32                 // 128-row tiles per batch
#define CHUNKS 128            // 32 row-tiles x 4 strips (circulant k-cover)
#define TILEB 16384           // 128 rows * 128 bytes (int8)

// Normalized rows scaled to int8 (q = round(127*zn)), [b][n][d] row-major
__device__ __align__(16) unsigned char g_zn[(size_t)B_ * N_ * D_];
// Per-row sum(2^d') and positive d' accumulators  (d' = 2*log2(e)*cos)
__device__ float g_rowsum[B_ * N_];
__device__ float g_rowpos[B_ * N_];

// ---------------------------------------------------------------- zero scratch
__global__ void zero_kernel(float* out, int n_out) {
    int i = blockIdx.x * blockDim.x + threadIdx.x;
    if (i < B_ * N_) { g_rowsum[i] = 0.f; g_rowpos[i] = 0.f; }
    if (i < n_out) out[i] = 0.f;
}

// ------------------------------------------------------- normalize + transpose
// Z[b][d][m] fp32 -> g_zn[b][n][d] int8 = round(127 * z/max(||z||,1e-8)).
__global__ void normalize_kernel(const float* __restrict__ Zi,
                                 const float* __restrict__ Zj) {
    __shared__ float tile[D_][33];
    __shared__ float part[8][32];
    __shared__ float rnorm_s[32];
    const int m0  = blockIdx.x * 32;
    const int src = blockIdx.y;
    const int b   = blockIdx.z;
    const float* Z = src ? Zj : Zi;
    const int tid = threadIdx.x;
    const int tx = tid & 31, ty = tid >> 5;

    const float* base = Z + (size_t)b * D_ * M_ + m0 + tx;
    float ss = 0.f;
#pragma unroll
    for (int d = ty; d < D_; d += 8) {
        float v = base[(size_t)d * M_];
        tile[d][tx] = v;
        ss += v * v;
    }
    part[ty][tx] = ss;
    __syncthreads();
    if (ty == 0) {
        float s = 0.f;
#pragma unroll
        for (int k = 0; k < 8; k++) s += part[k][tx];
        rnorm_s[tx] = 127.0f / fmaxf(sqrtf(s), 1e-8f);
    }
    __syncthreads();

    unsigned* out32 = reinterpret_cast<unsigned*>(g_zn);
    const size_t nbase = (size_t)b * N_ + (size_t)src * M_ + m0;
#pragma unroll
    for (int it = 0; it < 4; it++) {
        int idx = it * 256 + tid;      // 0..1023
        int r = idx >> 5;              // row 0..31
        int q = idx & 31;              // d-quad 0..31
        float rn = rnorm_s[r];
        int q0, q1, q2, q3;
        asm("cvt.rni.sat.s8.f32 %0, %1;" : "=r"(q0) : "f"(tile[4 * q][r] * rn));
        asm("cvt.rni.sat.s8.f32 %0, %1;" : "=r"(q1) : "f"(tile[4 * q + 1][r] * rn));
        asm("cvt.rni.sat.s8.f32 %0, %1;" : "=r"(q2) : "f"(tile[4 * q + 2][r] * rn));
        asm("cvt.rni.sat.s8.f32 %0, %1;" : "=r"(q3) : "f"(tile[4 * q + 3][r] * rn));
        unsigned pk = (q0 & 0xff) | ((q1 & 0xff) << 8)
                    | ((q2 & 0xff) << 16) | ((q3 & 0xff) << 24);
        out32[(nbase + r) * 32 + q] = pk;
    }
}

// ------------------------------------------------------------------- helpers
__device__ __forceinline__ unsigned swz_off(int row, int ch) {
    // 128B rows, 8 chunks of 16B, XOR swizzle -> conflict-free ldmatrix
    return (unsigned)(row * 128 + ((ch ^ (row & 7)) << 4));
}
__device__ __forceinline__ void ldsm_x4(unsigned addr, unsigned& r0, unsigned& r1,
                                        unsigned& r2, unsigned& r3) {
    asm volatile("ldmatrix.sync.aligned.m8n8.x4.shared.b16 {%0,%1,%2,%3}, [%4];"
                 : "=r"(r0), "=r"(r1), "=r"(r2), "=r"(r3) : "r"(addr));
}
__device__ __forceinline__ void mma_s8(int* c, const unsigned* a,
                                       unsigned b0, unsigned b1) {
    asm volatile("mma.sync.aligned.m16n8k32.row.col.s32.s8.s8.s32 "
                 "{%0,%1,%2,%3}, {%4,%5,%6,%7}, {%8,%9}, {%0,%1,%2,%3};"
                 : "+r"(c[0]), "+r"(c[1]), "+r"(c[2]), "+r"(c[3])
                 : "r"(a[0]), "r"(a[1]), "r"(a[2]), "r"(a[3]), "r"(b0), "r"(b1));
}
__device__ __forceinline__ float ex2f(float x) {
    float y; asm("ex2.approx.f32 %0, %1;" : "=f"(y) : "f"(x)); return y;
}
__device__ __forceinline__ float lg2f(float x) {
    float y; asm("lg2.approx.f32 %0, %1;" : "=f"(y) : "f"(x)); return y;
}
__device__ __forceinline__ void cp16(unsigned dst, const void* src) {
    asm volatile("cp.async.cg.shared.global [%0], [%1], 16;"
                 :: "r"(dst), "l"(src) : "memory");
}
#define CP_COMMIT() asm volatile("cp.async.commit_group;" ::: "memory")

__device__ __forceinline__ void load_tile(unsigned sdst, const char* gsrc, int tid) {
#pragma unroll
    for (int it = 0; it < 4; it++) {
        int idx = it * 256 + tid;          // 1024 x 16B chunks
        int row = idx >> 3, ch = idx & 7;
        cp16(sdst + swz_off(row, ch), gsrc + row * 128 + ch * 16);
    }
}

// ------------------------------------------------------------------ main pass
// Circulant pair cover: CTA = (row-tile i, strip s). Strip s covers
// k = 4s..4s+3 (plus k=16 appended to s=3 for i<16); col tile j=(i+k)&31.
// Every unordered tile pair covered exactly once; uniform CTA work.
__global__ __launch_bounds__(256, 2) void simclr_chunk_kernel() {
    extern __shared__ char smem[];          // A 16K | B0 | B1 | B2 (16K each)
    __shared__ float csum[4][128];
    __shared__ float asum[128], apos[128];

    const int b = blockIdx.y;
    const int ti = blockIdx.x >> 2;
    const int s  = blockIdx.x & 3;
    const int k0 = s * 4;
    const bool has16 = (s == 3 && ti < 16);
    const int nt = has16 ? 5 : 4;

    const int tid = threadIdx.x;
    const int lane = tid & 31, w = tid >> 5;
    const int rowA = (w >> 1) * 32;
    const int colB = (w & 1) * 64;

    unsigned sA = (unsigned)__cvta_generic_to_shared(smem);
    unsigned sB[3] = {sA + 16384, sA + 32768, sA + 49152};

    if (tid < 128) { asum[tid] = 0.f; apos[tid] = 0.f; }

    const char* zb = (const char*)(g_zn + (size_t)b * N_ * D_);
    load_tile(sA, zb + (size_t)ti * TILEB, tid);
    load_tile(sB[0], zb + (size_t)(((ti + k0) & 31)) * TILEB, tid);
    CP_COMMIT();
    load_tile(sB[1], zb + (size_t)(((ti + k0 + 1) & 31)) * TILEB, tid);
    CP_COMMIT();
    load_tile(sB[2], zb + (size_t)(((ti + k0 + 2) & 31)) * TILEB, tid);
    CP_COMMIT();

    float rs[4] = {0.f, 0.f, 0.f, 0.f};
    float* rowsum_b = g_rowsum + b * N_;
    float* rowpos_b = g_rowpos + b * N_;
    const float K = 2.885390081777927f / 16129.0f;  // 2*log2(e) / 127^2

    int bufi = 0;
    for (int t = 0; t < nt; t++) {
        asm volatile("cp.async.wait_group 2;" ::: "memory");
        __syncthreads();

        const int kk = k0 + t;
        const int j = (ti + kk) & 31;
        const unsigned sBt = sB[bufi];
        const bool dt = (kk == 0);
        const bool pt = (kk == 16);

        int acc[2][8][4];
#pragma unroll
        for (int mi = 0; mi < 2; mi++)
#pragma unroll
            for (int ng = 0; ng < 8; ng++)
#pragma unroll
                for (int q = 0; q < 4; q++) acc[mi][ng][q] = 0;

#pragma unroll
        for (int k = 0; k < 4; k++) {            // k32 per step
            unsigned a[2][4], bb[4][4];
            const int ch = 2 * k + (lane >> 4);
            const int rl = lane & 15;
#pragma unroll
            for (int mi = 0; mi < 2; mi++)
                ldsm_x4(sA + swz_off(rowA + mi * 16 + rl, ch),
                        a[mi][0], a[mi][1], a[mi][2], a[mi][3]);
#pragma unroll
            for (int g = 0; g < 4; g++)
                ldsm_x4(sBt + swz_off(colB + g * 16 + rl, ch),
                        bb[g][0], bb[g][1], bb[g][2], bb[g][3]);
#pragma unroll
            for (int mi = 0; mi < 2; mi++)
#pragma unroll
                for (int ng = 0; ng < 8; ng++)
                    mma_s8(acc[mi][ng], a[mi],
                           bb[ng >> 1][ng & 1], bb[ng >> 1][(ng & 1) + 2]);
        }

        // transform in place: int acc -> float exp2(K*acc) (bit-cast storage)
        if (!dt && !pt) {
#pragma unroll
            for (int mi = 0; mi < 2; mi++)
#pragma unroll
                for (int ng = 0; ng < 8; ng++)
#pragma unroll
                    for (int q = 0; q < 4; q++)
                        acc[mi][ng][q] = __float_as_int(
                            ex2f((float)acc[mi][ng][q] * K));
        } else {
#pragma unroll
            for (int mi = 0; mi < 2; mi++)
#pragma unroll
                for (int ng = 0; ng < 8; ng++)
#pragma unroll
                    for (int q = 0; q < 4; q++) {
                        const int lr = rowA + mi * 16 + (q >> 1) * 8 + (lane >> 2);
                        const int lc = colB + ng * 8 + ((lane & 3) << 1) + (q & 1);
                        const float dv = (float)acc[mi][ng][q] * K;
                        if (pt && lr == lc) {
                            atomicAdd(&apos[lr], dv);
                            atomicAdd(&rowpos_b[j * 128 + lr], dv);
                        }
                        acc[mi][ng][q] = __float_as_int(
                            (dt && lr == lc) ? 0.f : ex2f(dv));
                    }
        }

        // row partials (registers, reduced at CTA end)
#pragma unroll
        for (int idx = 0; idx < 4; idx++) {
            const int mi = idx >> 1, qh = idx & 1;
            float r = 0.f;
#pragma unroll
            for (int ng = 0; ng < 8; ng++)
                r += __int_as_float(acc[mi][ng][2 * qh])
                   + __int_as_float(acc[mi][ng][2 * qh + 1]);
            rs[idx] += r;
        }

        // column partials -> csum (conflict-free slots)
#pragma unroll
        for (int ng = 0; ng < 8; ng++)
#pragma unroll
            for (int ql = 0; ql < 2; ql++) {
                float cs = __int_as_float(acc[0][ng][ql])
                         + __int_as_float(acc[0][ng][ql + 2])
                         + __int_as_float(acc[1][ng][ql])
                         + __int_as_float(acc[1][ng][ql + 2]);
                cs += __shfl_xor_sync(0xffffffffu, cs, 4);
                cs += __shfl_xor_sync(0xffffffffu, cs, 8);
                cs += __shfl_xor_sync(0xffffffffu, cs, 16);
                if (lane < 4)
                    csum[w >> 1][colB + ng * 8 + lane * 2 + ql] = cs;
            }
        __syncthreads();

        // prefetch B_{t+3} into the buffer just consumed
        if (t + 3 < nt)
            load_tile(sB[bufi], zb + (size_t)(((ti + k0 + t + 3) & 31)) * TILEB, tid);
        CP_COMMIT();

        // push column sums to rows of tile j (skip diagonal tile)
        if (!dt && tid < 128) {
            float cs = (csum[0][tid] + csum[1][tid])
                     + (csum[2][tid] + csum[3][tid]);
            atomicAdd(&rowsum_b[j * 128 + tid], cs);
        }
        bufi = (bufi == 2) ? 0 : bufi + 1;
    }

    // CTA-end: quad-reduce row partials, combine, push rows of tile ti
#pragma unroll
    for (int idx = 0; idx < 4; idx++) {
        rs[idx] += __shfl_xor_sync(0xffffffffu, rs[idx], 1);
        rs[idx] += __shfl_xor_sync(0xffffffffu, rs[idx], 2);
    }
    if ((lane & 3) == 0) {
#pragma unroll
        for (int idx = 0; idx < 4; idx++)
            atomicAdd(&asum[rowA + (idx >> 1) * 16 + (idx & 1) * 8 + (lane >> 2)],
                      rs[idx]);
    }
    __syncthreads();
    if (tid < 128) {
        atomicAdd(&rowsum_b[ti * 128 + tid], asum[tid]);
        if (has16) atomicAdd(&rowpos_b[ti * 128 + tid], apos[tid]);
    }
}

// -------------------------------------------------------------------- finalize
// loss_row = ln2 * (log2(rowsum) - rowpos)
__global__ void finalize_kernel(float* __restrict__ out) {
    const int r = blockIdx.x * 256 + threadIdx.x;
    float v = 0.6931471805599453f * (lg2f(g_rowsum[r]) - g_rowpos[r]);
#pragma unroll
    for (int o = 16; o > 0; o >>= 1) v += __shfl_xor_sync(0xffffffffu, v, o);
    __shared__ float red[8];
    const int w = threadIdx.x >> 5;
    if ((threadIdx.x & 31) == 0) red[w] = v;
    __syncthreads();
    if (threadIdx.x == 0) {
        float s = 0.f;
#pragma unroll
        for (int k = 0; k < 8; k++) s += red[k];
        atomicAdd(out, s * (1.f / ((float)B_ * (float)N_)));
    }
}

// ----------------------------------------------------------------- entry point
extern "C" void kernel_launch(void* const* d_in, const int* in_sizes, int n_in,
                              void* d_out, int out_size) {
    const float* Zi = (const float*)d_in[0];
    const float* Zj = (const float*)d_in[1];
    float* out = (float*)d_out;
    (void)in_sizes; (void)n_in;

    cudaFuncSetAttribute(simclr_chunk_kernel,
                         cudaFuncAttributeMaxDynamicSharedMemorySize, 65536);

    zero_kernel<<<(B_ * N_ + 255) / 256, 256>>>(out, out_size);
    normalize_kernel<<<dim3(M_ / 32, 2, B_), 256>>>(Zi, Zj);
    simclr_chunk_kernel<<<dim3(CHUNKS, B_), 256, 65536>>>();
    finalize_kernel<<<B_ * N_ / 256, 256>>>(out);
}